// round 8
// baseline (speedup 1.0000x reference)
#include <cuda_runtime.h>
#include <cstdint>

#define B 8
#define C 64
#define H 128
#define W 128
#define HW (H * W)            // 16384
#define BHW (B * HW)          // 131072
#define NEVAL 17

#define OUT_TFM_OFF 2
#define OUT_IFM_OFF (2 + BHW)

struct LamParams {
    float lam[4][9];
};

// per-(eval, batch*block) partials: 17 x (8*64)
__device__ double g_part[NEVAL][512];

// ---------------------------------------------------------------------------
// Kernel 1: calc_fmap v5 — warp = half image row, 2 px/thread (float2 loads).
//   Block 256 thr = 8 warps = 4 rows x 2 halves. Grid (H/4, 2*B) = (32,16).
//   Halo: intra-warp shuffles; warp-seam column via 1 predicated scalar LDG
//   per row per channel. No smem in the loop, no barriers.
// ---------------------------------------------------------------------------
__global__ __launch_bounds__(256, 3)
void fmap_kernel(const float* __restrict__ tfeat, const float* __restrict__ ifeat,
                 float* __restrict__ out)
{
    const int z = blockIdx.y;                 // 0..15
    const int b = z & 7;
    const float* xb = ((z < B) ? tfeat : ifeat) + (size_t)b * C * HW;
    float* ob = out + (size_t)z * HW;

    const int w    = threadIdx.x >> 5;        // 0..7
    const int lane = threadIdx.x & 31;
    const int y    = blockIdx.x * 4 + (w & 3);
    const int half = w >> 2;                  // 0: x 0..63, 1: x 64..127
    const int x0   = half * 64 + lane * 2;

    const bool r0ok = (y > 0);
    const bool r2ok = (y < H - 1);
    const bool rok[3] = { r0ok, true, r2ok };

    // seam column: half 0 needs x=64 (lane31), half 1 needs x=63 (lane0)
    const int  xe  = half ? 63 : 64;
    const bool eok = half ? (lane == 0) : (lane == 31);

    const float* prow[3];
    prow[0] = xb + (size_t)(y - 1) * W;
    prow[1] = xb + (size_t)y * W;
    prow[2] = xb + (size_t)(y + 1) * W;

    float A0[9], A1[9];
    float P[3][2], Q[3][2], PE[3], QE[3];
#pragma unroll
    for (int k = 0; k < 9; k++) { A0[k] = 0.f; A1[k] = 0.f; }
#pragma unroll
    for (int r = 0; r < 3; r++) {
        P[r][0] = 0.f; P[r][1] = 0.f;
        Q[r][0] = 0.f; Q[r][1] = 0.f;
        PE[r] = 0.f;   QE[r] = 0.f;
    }

    for (int c = 0; c < C; c++) {
        const size_t co = (size_t)c * HW;
        float2 v[3];
        float  ev[3];
#pragma unroll
        for (int r = 0; r < 3; r++) {
            v[r]  = rok[r] ? __ldg((const float2*)(prow[r] + co + x0))
                           : make_float2(0.f, 0.f);
            ev[r] = (eok && rok[r]) ? __ldg(prow[r] + co + xe) : 0.f;
        }

        float rs0[3], rs1[3];
        float Lv[3], Rv[3];
#pragma unroll
        for (int r = 0; r < 3; r++) {
            float L = __shfl_up_sync(0xffffffffu, v[r].y, 1);
            float R = __shfl_down_sync(0xffffffffu, v[r].x, 1);
            if (lane == 0)  L = half ? ev[r] : 0.f;
            if (lane == 31) R = half ? 0.f : ev[r];
            Lv[r] = L; Rv[r] = R;
            float m = v[r].x + v[r].y;
            rs0[r] = L + m;
            rs1[r] = m + R;
            P[r][0] += v[r].x;  P[r][1] += v[r].y;
            Q[r][0] = fmaf(v[r].x, v[r].x, Q[r][0]);
            Q[r][1] = fmaf(v[r].y, v[r].y, Q[r][1]);
            PE[r] += ev[r];
            QE[r] = fmaf(ev[r], ev[r], QE[r]);
        }
        float s0 = rs0[0] + rs0[1] + rs0[2];
        float s1 = rs1[0] + rs1[1] + rs1[2];

#pragma unroll
        for (int r = 0; r < 3; r++) {
            A0[3 * r + 0] = fmaf(Lv[r],   s0, A0[3 * r + 0]);
            A0[3 * r + 1] = fmaf(v[r].x,  s0, A0[3 * r + 1]);
            A0[3 * r + 2] = fmaf(v[r].y,  s0, A0[3 * r + 2]);
            A1[3 * r + 0] = fmaf(v[r].x,  s1, A1[3 * r + 0]);
            A1[3 * r + 1] = fmaf(v[r].y,  s1, A1[3 * r + 1]);
            A1[3 * r + 2] = fmaf(Rv[r],   s1, A1[3 * r + 2]);
        }
    }

    // halo exchange of P/Q: columns x0-1 and x0+2
    float PL[3], PR[3], QL[3], QR[3];
#pragma unroll
    for (int r = 0; r < 3; r++) {
        PL[r] = __shfl_up_sync(0xffffffffu, P[r][1], 1);
        QL[r] = __shfl_up_sync(0xffffffffu, Q[r][1], 1);
        PR[r] = __shfl_down_sync(0xffffffffu, P[r][0], 1);
        QR[r] = __shfl_down_sync(0xffffffffu, Q[r][0], 1);
        if (lane == 0)  { PL[r] = half ? PE[r] : 0.f; QL[r] = half ? QE[r] : 0.f; }
        if (lane == 31) { PR[r] = half ? 0.f : PE[r]; QR[r] = half ? 0.f : QE[r]; }
    }

    float res[2];
#pragma unroll
    for (int i = 0; i < 2; i++) {
        const float* Ak = i ? A1 : A0;
        float S1[9], T2 = 0.f;
#pragma unroll
        for (int r = 0; r < 3; r++) {
            float p0 = i ? P[r][0] : PL[r];
            float p1 = i ? P[r][1] : P[r][0];
            float p2 = i ? PR[r]   : P[r][1];
            float q0 = i ? Q[r][0] : QL[r];
            float q1 = i ? Q[r][1] : Q[r][0];
            float q2 = i ? QR[r]   : Q[r][1];
            S1[3 * r + 0] = p0;
            S1[3 * r + 1] = p1;
            S1[3 * r + 2] = p2;
            T2 += q0 + q1 + q2;
        }
        float mu[9], M = 0.f, musq = 0.f;
#pragma unroll
        for (int k = 0; k < 9; k++) {
            mu[k] = S1[k] * (1.f / C);
            M += mu[k];
            musq = fmaf(mu[k], mu[k], musq);
        }
        float trace = T2 - (float)C * musq;

        float rmax = -3.4e38f, rmin = 3.4e38f;
#pragma unroll
        for (int k = 0; k < 9; k++) {
            float rsv = Ak[k] - (float)C * mu[k] * M;
            rmax = fmaxf(rmax, rsv);
            rmin = fminf(rmin, rsv);
        }
        res[i] = (rmax + rmin) * 0.5f / trace;
    }
    float* op = ob + (size_t)y * W + x0;
    op[0] = res[0];
    op[1] = res[1];
}

// ---------------------------------------------------------------------------
// Kernel 2: warp + ssim, all 17 evals per thread (high MLP), fp32 reduce.
//   Grid (HW/256 = 64, B = 8), block 256.
// ---------------------------------------------------------------------------
__global__ __launch_bounds__(256)
void ssim_kernel(const float* __restrict__ tfm, const float* __restrict__ ifm,
                 const float* __restrict__ tw,  const float* __restrict__ iw,
                 const float* __restrict__ Hgt, LamParams P)
{
    const int b   = blockIdx.y;
    const int idx = blockIdx.x * 256 + threadIdx.x;

    float Hg[9];
#pragma unroll
    for (int i = 0; i < 9; i++)
        Hg[i] = __ldg(&Hgt[b * 9 + i]);

    const int y = idx >> 7;
    const int x = idx & 127;
    const float fx = (float)x, fy = (float)y;

    const float* fb  = ifm + (size_t)b * HW;
    const float* wbp = iw  + (size_t)b * HW;
    const float t0   = __ldg(&tfm[(size_t)b * HW + idx]);
    const float tw0  = __ldg(&tw[(size_t)b * HW + idx]);

    float acc[NEVAL];

#pragma unroll
    for (int e = 0; e < NEVAL; e++) {
        float cf = 0.f;
        int n = 0;
        if (e > 0) {
            n = (e - 1) >> 2;
            const int j = (e - 1) & 3;
            cf = (j == 0) ? 1.f : (j == 1) ? 2.f : (j == 2) ? -1.f : -2.f;
        }
        float Hm[9];
#pragma unroll
        for (int i = 0; i < 9; i++)
            Hm[i] = Hg[i] * (1.f + cf * P.lam[n][i]);

        float Z  = fmaf(Hm[6], fx, fmaf(Hm[7], fy, Hm[8]));
        float Xp = fmaf(Hm[0], fx, fmaf(Hm[1], fy, Hm[2]));
        float Yp = fmaf(Hm[3], fx, fmaf(Hm[4], fy, Hm[5]));
        float invZ = __fdividef(1.f, Z);
        float px = Xp * invZ;
        float py = Yp * invZ;

        float x0f = floorf(px), y0f = floorf(py);
        float x1f = x0f + 1.f,  y1f = y0f + 1.f;
        float wa = (x1f - px) * (y1f - py);
        float wb = (x1f - px) * (py - y0f);
        float wc = (px - x0f) * (y1f - py);
        float wd = (px - x0f) * (py - y0f);

        float wfm = 0.f, ww = 0.f;
#pragma unroll
        for (int t = 0; t < 4; t++) {
            float xi = (t & 2) ? x1f : x0f;
            float yi = (t & 1) ? y1f : y0f;
            float wt = (t == 0) ? wa : (t == 1) ? wb : (t == 2) ? wc : wd;
            float valid = (xi >= 0.f && xi <= (float)(W - 1) &&
                           yi >= 0.f && yi <= (float)(H - 1)) ? 1.f : 0.f;
            int xc = (int)fminf(fmaxf(xi, 0.f), (float)(W - 1));
            int yc = (int)fminf(fmaxf(yi, 0.f), (float)(H - 1));
            int off = yc * W + xc;
            wfm = fmaf(wt, __ldg(&fb[off])  * valid, wfm);
            ww  = fmaf(wt, __ldg(&wbp[off]) * valid, ww);
        }
        float d = t0 - wfm;
        acc[e] = (tw0 * ww) * (d * d);
    }

    // reduce all 17 sums
    const int lane = threadIdx.x & 31;
    const int warp = threadIdx.x >> 5;
    __shared__ float wsum[8][NEVAL];
#pragma unroll
    for (int e = 0; e < NEVAL; e++) {
        float v = acc[e];
#pragma unroll
        for (int o = 16; o > 0; o >>= 1)
            v += __shfl_down_sync(0xffffffffu, v, o);
        if (lane == 0) wsum[warp][e] = v;
    }
    __syncthreads();
    if (threadIdx.x < NEVAL) {
        const int e = threadIdx.x;
        float s = 0.f;
#pragma unroll
        for (int w2 = 0; w2 < 8; w2++) s += wsum[w2][e];
        g_part[e][b * 64 + blockIdx.x] = (double)s;
    }
}

// ---------------------------------------------------------------------------
// Kernel 3: final reduce + combine (single block, 512 threads)
// ---------------------------------------------------------------------------
__global__ __launch_bounds__(512)
void final_kernel(float* __restrict__ out, LamParams P)
{
    __shared__ double sums[NEVAL];
    __shared__ double wred[16];
    const int t = threadIdx.x;
    const int lane = t & 31, warp = t >> 5;

    for (int e = 0; e < NEVAL; e++) {
        double s = g_part[e][t];
#pragma unroll
        for (int o = 16; o > 0; o >>= 1)
            s += __shfl_down_sync(0xffffffffu, s, o);
        if (lane == 0) wred[warp] = s;
        __syncthreads();
        if (warp == 0) {
            double v = (lane < 16) ? wred[lane] : 0.0;
#pragma unroll
            for (int o = 8; o > 0; o >>= 1)
                v += __shfl_down_sync(0xffffffffu, v, o);
            if (lane == 0) sums[e] = v;
        }
        __syncthreads();
    }

    if (t == 0) {
        const double inv = 1.0 / (double)BHW;
        double mid = sums[0] * inv;
        double loss = 0.0;
#pragma unroll
        for (int n = 0; n < 4; n++) {
            double sL  = sums[1 + 4 * n] * inv;
            double sLL = sums[2 + 4 * n] * inv;
            double sR  = sums[3 + 4 * n] * inv;
            double sRR = sums[4 + 4 * n] * inv;
            float s2f = 0.f;
#pragma unroll
            for (int i = 0; i < 9; i++) s2f = fmaf(P.lam[n][i], P.lam[n][i], s2f);
            double s2 = (double)s2f;
            double d2 = 3.0 * s2;
            loss -= fmin(sL - mid - s2, 0.0);
            loss -= fmin(sL - sLL + d2, 0.0);
            loss -= fmin(sR - mid - s2, 0.0);
            loss -= fmin(sR - sRR + d2, 0.0);
        }
        out[0] = (float)loss;
        out[1] = (float)mid;
    }
}

// ---------------------------------------------------------------------------
// Host: JAX Threefry (partitionable) for gen_lambda
// ---------------------------------------------------------------------------
static inline void threefry2x32(uint32_t k0, uint32_t k1,
                                uint32_t x0, uint32_t x1,
                                uint32_t* o0, uint32_t* o1)
{
    const uint32_t ks[3] = {k0, k1, k0 ^ k1 ^ 0x1BD11BDAu};
    uint32_t v0 = x0 + ks[0];
    uint32_t v1 = x1 + ks[1];
    static const int rot[2][4] = {{13, 15, 26, 6}, {17, 29, 16, 24}};
    for (int g = 0; g < 5; g++) {
        const int* r = rot[g & 1];
        for (int i = 0; i < 4; i++) {
            v0 += v1;
            v1 = (v1 << r[i]) | (v1 >> (32 - r[i]));
            v1 ^= v0;
        }
        v0 += ks[(g + 1) % 3];
        v1 += ks[(g + 2) % 3] + (uint32_t)(g + 1);
    }
    *o0 = v0;
    *o1 = v1;
}

static void compute_lambdas(LamParams* P)
{
    for (int n = 0; n < 4; n++) {
        uint32_t k0, k1;
        threefry2x32(0u, 42u, 0u, (uint32_t)n, &k0, &k1);
        for (int i = 0; i < 9; i++) {
            uint32_t o0, o1;
            threefry2x32(k0, k1, 0u, (uint32_t)i, &o0, &o1);
            uint32_t bits = o0 ^ o1;
            uint32_t fb = (bits >> 9) | 0x3f800000u;
            float u;
            __builtin_memcpy(&u, &fb, 4);
            u -= 1.0f;
            float lam = (u - 0.5f) / 6.0f;
            if (lam > 0.f && lam < 0.02f)  lam = 0.02f;
            if (lam < 0.f && lam > -0.02f) lam = -0.02f;
            P->lam[n][i] = lam;
        }
        P->lam[n][8] = 0.0f;
    }
}

// ---------------------------------------------------------------------------
// Entry point
// ---------------------------------------------------------------------------
extern "C" void kernel_launch(void* const* d_in, const int* in_sizes, int n_in,
                              void* d_out, int out_size)
{
    (void)in_sizes; (void)n_in; (void)out_size;
    const float* tfeat = (const float*)d_in[0];
    const float* ifeat = (const float*)d_in[1];
    const float* tw    = (const float*)d_in[2];
    const float* iw    = (const float*)d_in[3];
    const float* Hgt   = (const float*)d_in[4];
    float* out = (float*)d_out;

    LamParams P;
    compute_lambdas(&P);

    float* tfm = out + OUT_TFM_OFF;
    float* ifm = out + OUT_IFM_OFF;

    dim3 fgrd(H / 4, 2 * B);              // (32, 16) = 512 blocks of 256
    fmap_kernel<<<fgrd, 256>>>(tfeat, ifeat, tfm);

    dim3 sgrd(HW / 256, B);               // (64, 8) = 512 blocks of 256
    ssim_kernel<<<sgrd, 256>>>(tfm, ifm, tw, iw, Hgt, P);

    final_kernel<<<1, 512>>>(out, P);
}